// round 16
// baseline (speedup 1.0000x reference)
#include <cuda_runtime.h>
#include <cuda_bf16.h>

// SpatialTransformer: 3D trilinear grid-sample, border padding, align_corners=True.
// img [2,1,160,192,224], flow [2,3,160,192,224], out [2,1,160,192,224].
//
// px = (x+flow0+1)*111.5 clamps to 223 (fx=0) for essentially all x>=8 ->
// bilinear on the x=223 border slice, held ENTIRELY in shared memory
// (160 x 197-padded floats, 126 KB; 197%32==5 spreads the warp's clustered
// (z0,y0) patch across distinct banks).
// Phase A: x in [8,224) warp-uniform fast path (4 LDS + 6 FFMA).
// Phase B: x in [0,8) mixed path (3.6% of voxels).
// R16: single fused kernel — each CTA fills its slab DIRECTLY from img
// (no separate extract kernel, no global slice, no inter-kernel barrier).

#define DD 160
#define HH 192
#define WW 224
#define HW (HH * WW)
#define NVOX (DD * HH * WW)     // 6,881,280
#define NB 2
#define ROWS (DD * HH)          // 30,720

#define SP 197                  // padded smem row stride; 197 % 32 == 5
#define SLICE_BYTES (DD * SP * 4)       // 126,080

#define CTAS_PER_B 74
#define GRID_MAIN (2 * CTAS_PER_B)      // 148
#define TPB 1024
#define GSTRIDE (CTAS_PER_B * TPB)      // 75,776

#define MAIN_G (ROWS * 54)      // 1,658,880 groups (x in [8,224), 4 voxels each)
#define EDGE_G (ROWS * 2)       // 61,440 groups (x in [0,8))

// general (non-border) trilinear sample for one voxel
__device__ __forceinline__ float sample_general(
    const float* __restrict__ im, float pxr,
    int y0, int z0, float fy, float fz)
{
    const float px = fmaxf(pxr, 0.0f);          // px < 223 on this path
    const float x0f = floorf(px);
    const float fx = px - x0f;
    const int x0 = (int)x0f;
    const int x1 = min(x0 + 1, WW - 1);
    const int y1 = min(y0 + 1, HH - 1);
    const int z1 = min(z0 + 1, DD - 1);

    const int zb0 = z0 * HW;
    const int zb1 = z1 * HW;
    const int yb0 = y0 * WW;
    const int yb1 = y1 * WW;

    const float c000 = __ldg(im + zb0 + yb0 + x0);
    const float c001 = __ldg(im + zb0 + yb0 + x1);
    const float c010 = __ldg(im + zb0 + yb1 + x0);
    const float c011 = __ldg(im + zb0 + yb1 + x1);
    const float c100 = __ldg(im + zb1 + yb0 + x0);
    const float c101 = __ldg(im + zb1 + yb0 + x1);
    const float c110 = __ldg(im + zb1 + yb1 + x0);
    const float c111 = __ldg(im + zb1 + yb1 + x1);

    const float c00 = c000 + (c001 - c000) * fx;
    const float c01 = c010 + (c011 - c010) * fx;
    const float c10 = c100 + (c101 - c100) * fx;
    const float c11 = c110 + (c111 - c110) * fx;
    const float c0 = c00 + (c01 - c00) * fy;
    const float c1 = c10 + (c11 - c10) * fy;
    return c0 + (c1 - c0) * fz;
}

__global__ __launch_bounds__(TPB, 1) void st3d_kernel(
    const float* __restrict__ img,
    const float* __restrict__ flow,
    float* __restrict__ out)
{
    extern __shared__ float s_slice[];   // [DD][SP]

    const int tid = threadIdx.x;
    const int cta = blockIdx.x;
    const int b = (cta >= CTAS_PER_B) ? 1 : 0;
    const int c = cta - b * CTAS_PER_B;

    const float* im = img + (size_t)b * NVOX;

    // ---- fill smem slice (row-padded) DIRECTLY from img's x=223 column ----
    {
        const float* col = im + (WW - 1);
        for (int idx = tid; idx < ROWS; idx += TPB) {
            const int z = idx / HH;
            const int y = idx - z * HH;
            s_slice[z * SP + y] = __ldg(col + z * HW + y * WW);
        }
    }
    __syncthreads();

    const float* fb = flow + (size_t)b * 3 * NVOX;
    float* ob = out + (size_t)b * NVOX;

    // ================= Phase A: x in [8,224) — warp-uniform fast path =========
    {
        int g = c * TPB + tid;
        bool valid = (g < MAIN_G);
        float4 nf0, nf1, nf2;
        int ni = 0;
        if (valid) {
            const int row = g / 54;
            ni = row * WW + 8 + (g - row * 54) * 4;
            nf0 = __ldcs(reinterpret_cast<const float4*>(fb + ni));
            nf1 = __ldcs(reinterpret_cast<const float4*>(fb + NVOX + ni));
            nf2 = __ldcs(reinterpret_cast<const float4*>(fb + 2 * NVOX + ni));
        }

        while (valid) {
            const int i = ni;
            const float4 f0 = nf0, f1 = nf1, f2 = nf2;

            // distance-1 register prefetch
            const int gn = g + GSTRIDE;
            const bool nvalid = (gn < MAIN_G);
            if (nvalid) {
                const int rown = gn / 54;
                ni = rown * WW + 8 + (gn - rown * 54) * 4;
                nf0 = __ldcs(reinterpret_cast<const float4*>(fb + ni));
                nf1 = __ldcs(reinterpret_cast<const float4*>(fb + NVOX + ni));
                nf2 = __ldcs(reinterpret_cast<const float4*>(fb + 2 * NVOX + ni));
            }

            const int z = i / HW;
            const int rem = i - z * HW;
            const int y = rem / WW;
            const int x = rem - y * WW;

            const float f0a[4] = {f0.x, f0.y, f0.z, f0.w};
            const float f1a[4] = {f1.x, f1.y, f1.z, f1.w};
            const float f2a[4] = {f2.x, f2.y, f2.z, f2.w};

            float oa[4];
            #pragma unroll
            for (int k = 0; k < 4; ++k) {
                const float pxr = ((float)(x + k) + f0a[k] + 1.0f) * 111.5f;

                float py = (float)y + f1a[k];
                float pz = (float)z + f2a[k];
                py = fminf(fmaxf(py, 0.0f), (float)(HH - 1));
                pz = fminf(fmaxf(pz, 0.0f), (float)(DD - 1));

                const float y0f = floorf(py);
                const float z0f = floorf(pz);
                const float fy = py - y0f;
                const float fz = pz - z0f;
                const int y0 = (int)y0f;
                const int z0 = (int)z0f;

                if (pxr >= (float)(WW - 1)) {   // uniform-true for x >= 8
                    const int y1 = min(y0 + 1, HH - 1);
                    const int z1 = min(z0 + 1, DD - 1);
                    const int r0 = z0 * SP;
                    const int r1 = z1 * SP;
                    const float v00 = s_slice[r0 + y0];
                    const float v01 = s_slice[r0 + y1];
                    const float v10 = s_slice[r1 + y0];
                    const float v11 = s_slice[r1 + y1];
                    const float c0 = v00 + (v01 - v00) * fy;
                    const float c1 = v10 + (v11 - v10) * fy;
                    oa[k] = c0 + (c1 - c0) * fz;
                } else {
                    oa[k] = sample_general(im, pxr, y0, z0, fy, fz);
                }
            }

            __stcs(reinterpret_cast<float4*>(ob + i),
                   make_float4(oa[0], oa[1], oa[2], oa[3]));

            g = gn;
            valid = nvalid;
        }
    }

    // ================= Phase B: x in [0,8) — mixed path (3.6% of voxels) ======
    for (int g = c * TPB + tid; g < EDGE_G; g += GSTRIDE) {
        const int row = g >> 1;
        const int gi = g & 1;
        const int i = row * WW + gi * 4;
        const int z = row / HH;
        const int y = row - z * HH;
        const int x = gi * 4;

        const float4 f0 = __ldcs(reinterpret_cast<const float4*>(fb + i));
        const float4 f1 = __ldcs(reinterpret_cast<const float4*>(fb + NVOX + i));
        const float4 f2 = __ldcs(reinterpret_cast<const float4*>(fb + 2 * NVOX + i));

        const float f0a[4] = {f0.x, f0.y, f0.z, f0.w};
        const float f1a[4] = {f1.x, f1.y, f1.z, f1.w};
        const float f2a[4] = {f2.x, f2.y, f2.z, f2.w};

        float oa[4];
        #pragma unroll
        for (int k = 0; k < 4; ++k) {
            const float pxr = ((float)(x + k) + f0a[k] + 1.0f) * 111.5f;

            float py = (float)y + f1a[k];
            float pz = (float)z + f2a[k];
            py = fminf(fmaxf(py, 0.0f), (float)(HH - 1));
            pz = fminf(fmaxf(pz, 0.0f), (float)(DD - 1));

            const float y0f = floorf(py);
            const float z0f = floorf(pz);
            const float fy = py - y0f;
            const float fz = pz - z0f;
            const int y0 = (int)y0f;
            const int z0 = (int)z0f;

            if (pxr >= (float)(WW - 1)) {
                const int y1 = min(y0 + 1, HH - 1);
                const int z1 = min(z0 + 1, DD - 1);
                const int r0 = z0 * SP;
                const int r1 = z1 * SP;
                const float v00 = s_slice[r0 + y0];
                const float v01 = s_slice[r0 + y1];
                const float v10 = s_slice[r1 + y0];
                const float v11 = s_slice[r1 + y1];
                const float c0 = v00 + (v01 - v00) * fy;
                const float c1 = v10 + (v11 - v10) * fy;
                oa[k] = c0 + (c1 - c0) * fz;
            } else {
                oa[k] = sample_general(im, pxr, y0, z0, fy, fz);
            }
        }

        __stcs(reinterpret_cast<float4*>(ob + i),
               make_float4(oa[0], oa[1], oa[2], oa[3]));
    }
}

extern "C" void kernel_launch(void* const* d_in, const int* in_sizes, int n_in,
                              void* d_out, int out_size)
{
    const float* img  = (const float*)d_in[0];
    const float* flow = (const float*)d_in[1];
    float* out = (float*)d_out;

    cudaFuncSetAttribute(st3d_kernel,
                         cudaFuncAttributeMaxDynamicSharedMemorySize, SLICE_BYTES);

    st3d_kernel<<<GRID_MAIN, TPB, SLICE_BYTES>>>(img, flow, out);
}

// round 17
// speedup vs baseline: 1.2610x; 1.2610x over previous
#include <cuda_runtime.h>
#include <cuda_bf16.h>

// SpatialTransformer: 3D trilinear grid-sample, border padding, align_corners=True.
// img [2,1,160,192,224], flow [2,3,160,192,224], out [2,1,160,192,224].
//
// px = (x+flow0+1)*111.5 clamps to 223 (fx=0) for essentially all x>=8 ->
// bilinear on the x=223 border slice, held ENTIRELY in shared memory
// (160 x 197-padded floats, 126 KB; 197%32==5 spreads the warp's clustered
// (z0,y0) patch across distinct banks).
// Phase A: x in [8,224) warp-uniform fast path (4 LDS + 6 FFMA).
// Phase B: x in [0,8) mixed path (3.6% of voxels).
// R17: extract kernel writes the PADDED layout so the main kernel's smem fill
// is a pure coalesced float4 copy (no per-element div/mod, 4x fewer loads).

#define DD 160
#define HH 192
#define WW 224
#define HW (HH * WW)
#define NVOX (DD * HH * WW)     // 6,881,280
#define NB 2
#define ROWS (DD * HH)          // 30,720

#define SP 197                  // padded row stride; 197 % 32 == 5
#define SLICE_FLOATS (DD * SP)  // 31,520 (multiple of 4: 197*160)
#define SLICE_BYTES (SLICE_FLOATS * 4)  // 126,080

#define CTAS_PER_B 74
#define GRID_MAIN (2 * CTAS_PER_B)      // 148
#define TPB 1024
#define GSTRIDE (CTAS_PER_B * TPB)      // 75,776

#define MAIN_G (ROWS * 54)      // 1,658,880 groups (x in [8,224), 4 voxels each)
#define EDGE_G (ROWS * 2)       // 61,440 groups (x in [0,8))

__device__ float g_bspad[NB * SLICE_FLOATS];  // padded [b][z*SP+y] border slice

__global__ __launch_bounds__(256) void extract_border_kernel(
    const float* __restrict__ img)
{
    int idx = blockIdx.x * blockDim.x + threadIdx.x;
    if (idx >= NB * ROWS) return;
    int b = idx / ROWS;
    int r = idx - b * ROWS;           // z*HH + y
    int z = r / HH;
    int y = r - z * HH;
    g_bspad[b * SLICE_FLOATS + z * SP + y] =
        img[(size_t)b * NVOX + (size_t)z * HW + y * WW + (WW - 1)];
}

// general (non-border) trilinear sample for one voxel
__device__ __forceinline__ float sample_general(
    const float* __restrict__ im, float pxr,
    int y0, int z0, float fy, float fz)
{
    const float px = fmaxf(pxr, 0.0f);          // px < 223 on this path
    const float x0f = floorf(px);
    const float fx = px - x0f;
    const int x0 = (int)x0f;
    const int x1 = min(x0 + 1, WW - 1);
    const int y1 = min(y0 + 1, HH - 1);
    const int z1 = min(z0 + 1, DD - 1);

    const int zb0 = z0 * HW;
    const int zb1 = z1 * HW;
    const int yb0 = y0 * WW;
    const int yb1 = y1 * WW;

    const float c000 = __ldg(im + zb0 + yb0 + x0);
    const float c001 = __ldg(im + zb0 + yb0 + x1);
    const float c010 = __ldg(im + zb0 + yb1 + x0);
    const float c011 = __ldg(im + zb0 + yb1 + x1);
    const float c100 = __ldg(im + zb1 + yb0 + x0);
    const float c101 = __ldg(im + zb1 + yb0 + x1);
    const float c110 = __ldg(im + zb1 + yb1 + x0);
    const float c111 = __ldg(im + zb1 + yb1 + x1);

    const float c00 = c000 + (c001 - c000) * fx;
    const float c01 = c010 + (c011 - c010) * fx;
    const float c10 = c100 + (c101 - c100) * fx;
    const float c11 = c110 + (c111 - c110) * fx;
    const float c0 = c00 + (c01 - c00) * fy;
    const float c1 = c10 + (c11 - c10) * fy;
    return c0 + (c1 - c0) * fz;
}

__global__ __launch_bounds__(TPB, 1) void st3d_kernel(
    const float* __restrict__ img,
    const float* __restrict__ flow,
    float* __restrict__ out)
{
    extern __shared__ float s_slice[];   // [DD][SP]

    const int tid = threadIdx.x;
    const int cta = blockIdx.x;
    const int b = (cta >= CTAS_PER_B) ? 1 : 0;
    const int c = cta - b * CTAS_PER_B;

    // ---- fill smem slice: pure coalesced float4 copy of padded global slice --
    {
        const float4* src = reinterpret_cast<const float4*>(g_bspad + b * SLICE_FLOATS);
        float4* dst = reinterpret_cast<float4*>(s_slice);
        for (int idx = tid; idx < SLICE_FLOATS / 4; idx += TPB)
            dst[idx] = __ldg(src + idx);
    }
    __syncthreads();

    const float* fb = flow + (size_t)b * 3 * NVOX;
    const float* im = img + (size_t)b * NVOX;
    float* ob = out + (size_t)b * NVOX;

    // ================= Phase A: x in [8,224) — warp-uniform fast path =========
    {
        int g = c * TPB + tid;
        bool valid = (g < MAIN_G);
        float4 nf0, nf1, nf2;
        int ni = 0;
        if (valid) {
            const int row = g / 54;
            ni = row * WW + 8 + (g - row * 54) * 4;
            nf0 = __ldcs(reinterpret_cast<const float4*>(fb + ni));
            nf1 = __ldcs(reinterpret_cast<const float4*>(fb + NVOX + ni));
            nf2 = __ldcs(reinterpret_cast<const float4*>(fb + 2 * NVOX + ni));
        }

        while (valid) {
            const int i = ni;
            const float4 f0 = nf0, f1 = nf1, f2 = nf2;

            // distance-1 register prefetch
            const int gn = g + GSTRIDE;
            const bool nvalid = (gn < MAIN_G);
            if (nvalid) {
                const int rown = gn / 54;
                ni = rown * WW + 8 + (gn - rown * 54) * 4;
                nf0 = __ldcs(reinterpret_cast<const float4*>(fb + ni));
                nf1 = __ldcs(reinterpret_cast<const float4*>(fb + NVOX + ni));
                nf2 = __ldcs(reinterpret_cast<const float4*>(fb + 2 * NVOX + ni));
            }

            const int z = i / HW;
            const int rem = i - z * HW;
            const int y = rem / WW;
            const int x = rem - y * WW;

            const float f0a[4] = {f0.x, f0.y, f0.z, f0.w};
            const float f1a[4] = {f1.x, f1.y, f1.z, f1.w};
            const float f2a[4] = {f2.x, f2.y, f2.z, f2.w};

            float oa[4];
            #pragma unroll
            for (int k = 0; k < 4; ++k) {
                const float pxr = ((float)(x + k) + f0a[k] + 1.0f) * 111.5f;

                float py = (float)y + f1a[k];
                float pz = (float)z + f2a[k];
                py = fminf(fmaxf(py, 0.0f), (float)(HH - 1));
                pz = fminf(fmaxf(pz, 0.0f), (float)(DD - 1));

                const float y0f = floorf(py);
                const float z0f = floorf(pz);
                const float fy = py - y0f;
                const float fz = pz - z0f;
                const int y0 = (int)y0f;
                const int z0 = (int)z0f;

                if (pxr >= (float)(WW - 1)) {   // uniform-true for x >= 8
                    const int y1 = min(y0 + 1, HH - 1);
                    const int z1 = min(z0 + 1, DD - 1);
                    const int r0 = z0 * SP;
                    const int r1 = z1 * SP;
                    const float v00 = s_slice[r0 + y0];
                    const float v01 = s_slice[r0 + y1];
                    const float v10 = s_slice[r1 + y0];
                    const float v11 = s_slice[r1 + y1];
                    const float c0 = v00 + (v01 - v00) * fy;
                    const float c1 = v10 + (v11 - v10) * fy;
                    oa[k] = c0 + (c1 - c0) * fz;
                } else {
                    oa[k] = sample_general(im, pxr, y0, z0, fy, fz);
                }
            }

            __stcs(reinterpret_cast<float4*>(ob + i),
                   make_float4(oa[0], oa[1], oa[2], oa[3]));

            g = gn;
            valid = nvalid;
        }
    }

    // ================= Phase B: x in [0,8) — mixed path (3.6% of voxels) ======
    for (int g = c * TPB + tid; g < EDGE_G; g += GSTRIDE) {
        const int row = g >> 1;
        const int gi = g & 1;
        const int i = row * WW + gi * 4;
        const int z = row / HH;
        const int y = row - z * HH;
        const int x = gi * 4;

        const float4 f0 = __ldcs(reinterpret_cast<const float4*>(fb + i));
        const float4 f1 = __ldcs(reinterpret_cast<const float4*>(fb + NVOX + i));
        const float4 f2 = __ldcs(reinterpret_cast<const float4*>(fb + 2 * NVOX + i));

        const float f0a[4] = {f0.x, f0.y, f0.z, f0.w};
        const float f1a[4] = {f1.x, f1.y, f1.z, f1.w};
        const float f2a[4] = {f2.x, f2.y, f2.z, f2.w};

        float oa[4];
        #pragma unroll
        for (int k = 0; k < 4; ++k) {
            const float pxr = ((float)(x + k) + f0a[k] + 1.0f) * 111.5f;

            float py = (float)y + f1a[k];
            float pz = (float)z + f2a[k];
            py = fminf(fmaxf(py, 0.0f), (float)(HH - 1));
            pz = fminf(fmaxf(pz, 0.0f), (float)(DD - 1));

            const float y0f = floorf(py);
            const float z0f = floorf(pz);
            const float fy = py - y0f;
            const float fz = pz - z0f;
            const int y0 = (int)y0f;
            const int z0 = (int)z0f;

            if (pxr >= (float)(WW - 1)) {
                const int y1 = min(y0 + 1, HH - 1);
                const int z1 = min(z0 + 1, DD - 1);
                const int r0 = z0 * SP;
                const int r1 = z1 * SP;
                const float v00 = s_slice[r0 + y0];
                const float v01 = s_slice[r0 + y1];
                const float v10 = s_slice[r1 + y0];
                const float v11 = s_slice[r1 + y1];
                const float c0 = v00 + (v01 - v00) * fy;
                const float c1 = v10 + (v11 - v10) * fy;
                oa[k] = c0 + (c1 - c0) * fz;
            } else {
                oa[k] = sample_general(im, pxr, y0, z0, fy, fz);
            }
        }

        __stcs(reinterpret_cast<float4*>(ob + i),
               make_float4(oa[0], oa[1], oa[2], oa[3]));
    }
}

extern "C" void kernel_launch(void* const* d_in, const int* in_sizes, int n_in,
                              void* d_out, int out_size)
{
    const float* img  = (const float*)d_in[0];
    const float* flow = (const float*)d_in[1];
    float* out = (float*)d_out;

    cudaFuncSetAttribute(st3d_kernel,
                         cudaFuncAttributeMaxDynamicSharedMemorySize, SLICE_BYTES);

    extract_border_kernel<<<(NB * ROWS + 255) / 256, 256>>>(img);
    st3d_kernel<<<GRID_MAIN, TPB, SLICE_BYTES>>>(img, flow, out);
}